// round 11
// baseline (speedup 1.0000x reference)
#include <cuda_runtime.h>
#include <cstdint>
#include <cstddef>

#define BATCH 8
#define NPTS  4096
#define CCH   128
#define HOUT  256
#define KNNK  16
#define ROWS  (BATCH * NPTS)

// ---------------- scratch (static __device__ — no runtime allocation) ----------------
__device__ float g_asrc[ROWS * CCH];
__device__ float g_adst[ROWS * CCH];
__device__ float g_val [ROWS * CCH];
__device__ float g_attn[ROWS * CCH];
__device__ int   g_knn [ROWS * KNNK];

// ---------------- packed f32x2 helpers ----------------
__device__ __forceinline__ unsigned long long dup2(float x) {
    unsigned long long r;
    asm("mov.b64 %0, {%1, %1};" : "=l"(r) : "f"(x));
    return r;
}
__device__ __forceinline__ void fma2(unsigned long long& d, unsigned long long a,
                                     unsigned long long b) {
    asm("fma.rn.f32x2 %0, %1, %2, %0;" : "+l"(d) : "l"(a), "l"(b));
}
__device__ __forceinline__ float2 unpack2(unsigned long long v) {
    float2 r;
    asm("mov.b64 {%0, %1}, %2;" : "=f"(r.x), "=f"(r.y) : "l"(v));
    return r;
}

// ---------------- KNN: warp per 4 rows, ONE ballot per tile ---------------------------
// Sorted top-16 keys (ascending) per row live in lanes 0..15, one u64 per lane:
//   key = (float_bits(d2) << 32) | j   (d2 >= 0: bit order == value order; ties by idx)
// Hot loop: 4 distances + 4 predicates -> OR -> single ballot. Zero (common case) skips
// everything. Per-row ballots + warp-uniform shfl_up inserts only run on passing tiles.
// th/tk may be stale (updated per passing tile): they only filter candidates that
// provably cannot enter the top-16; sorted-insert of a non-qualifying cand is a no-op.
__global__ __launch_bounds__(256) void knn_kernel(const float* __restrict__ pos) {
    __shared__ float2 sxy[NPTS];   // 32 KB
    __shared__ float  szv[NPTS];   // 16 KB

    const int bpb = NPTS / 32;            // 32 rows per block
    int b  = blockIdx.x / bpb;
    int rb = blockIdx.x % bpb;
    const float* pb = pos + (size_t)b * NPTS * 3;

    for (int t = threadIdx.x; t < NPTS; t += 256) {
        const float* p = pb + t * 3;
        sxy[t] = make_float2(p[0], p[1]);
        szv[t] = p[2];
    }
    __syncthreads();

    int warp = threadIdx.x >> 5;
    int lane = threadIdx.x & 31;
    const unsigned FULL = 0xffffffffu;
    int i0 = rb * 32 + warp * 4;          // this warp's 4 rows

    float3 pi[4];
    unsigned long long cur[4], tk[4];
    float th[4];
#pragma unroll
    for (int r = 0; r < 4; r++) {
        float2 q = sxy[i0 + r];
        pi[r] = make_float3(q.x, q.y, szv[i0 + r]);
        cur[r] = ~0ull;
        tk[r]  = ~0ull;
        th[r]  = __int_as_float(0x7f800000);   // +inf
    }

    for (int j0 = 0; j0 < NPTS; j0 += 32) {
        int j = j0 + lane;
        float2 pj = sxy[j];
        float  zj = szv[j];

        float d2v[4];
        bool  pr[4];
#pragma unroll
        for (int r = 0; r < 4; r++) {
            float dx = pi[r].x - pj.x;
            float dy = pi[r].y - pj.y;
            float dz = pi[r].z - zj;
            d2v[r] = fmaf(dx, dx, fmaf(dy, dy, dz * dz));
            pr[r]  = d2v[r] <= th[r];
        }

        // single ballot on the disjunction: zero -> whole tile skipped
        unsigned any = __ballot_sync(FULL, pr[0] | pr[1] | pr[2] | pr[3]);
        if (any) {                                           // warp-uniform
#pragma unroll
            for (int r = 0; r < 4; r++) {
                unsigned mask = __ballot_sync(FULL, pr[r]);  // per-row, slow path only
                if (mask) {                                   // warp-uniform
                    unsigned long long key =
                        ((unsigned long long)__float_as_uint(d2v[r]) << 32) | (unsigned)j;
                    bool changed = false;
                    while (mask) {                            // warp-uniform
                        int src = __ffs(mask) - 1;
                        mask &= mask - 1;
                        unsigned long long cand = __shfl_sync(FULL, key, src);
                        if (cand < tk[r]) {   // stale gate (exact-superset filter)
                            unsigned long long prev = __shfl_up_sync(FULL, cur[r], 1);
                            bool bigger = cur[r] > cand;
                            unsigned long long ins =
                                (lane > 0 && prev > cand) ? prev : cand;
                            cur[r] = bigger ? ins : cur[r];   // no-op if cand >= lane15
                            changed = true;
                        }
                    }
                    if (changed) {                            // warp-uniform
                        tk[r] = __shfl_sync(FULL, cur[r], 15);
                        th[r] = __uint_as_float((unsigned)(tk[r] >> 32));
                    }
                }
            }
        }
    }

    if (lane < KNNK) {
#pragma unroll
        for (int r = 0; r < 4; r++)
            g_knn[((size_t)b * NPTS + i0 + r) * KNNK + lane] =
                (int)(unsigned)(cur[r] & 0xffffffffu);
    }
}

// ---------------- GEMM core (R4-exact): C = A[Mx128] @ B[128xN] (+bias) --------------
// 256 threads, tile 128M x 64N, 8M x 4N per thread (f32x2 pairs over M). Measured:
// 51.7-53.5us gemm_out, regs=76, occ=33%, fma=58%.
#define GBM 128
#define GBN 64
#define GBK 32
#define SAS 130   // padded (even) stride for transposed A tile

template <int N>
__device__ __forceinline__ void gemm_body(const float* __restrict__ A,
                                          const float* __restrict__ B,
                                          const float* __restrict__ bias,
                                          float* __restrict__ C,
                                          int m0, int n0) {
    __shared__ float sA[GBK * SAS];   // [k][m] transposed, ~16.6 KB
    __shared__ float sB[GBK * GBN];   // [k][n], 8 KB

    int tid = threadIdx.x;
    int tx  = tid & 15;        // n: 16 threads * 4 cols
    int ty  = tid >> 4;        // m: 16 threads * 8 rows

    unsigned long long acc[4][4];
#pragma unroll
    for (int i = 0; i < 4; i++)
#pragma unroll
        for (int j = 0; j < 4; j++) acc[i][j] = 0ull;   // bits of (0.f, 0.f)

    for (int k0 = 0; k0 < CCH; k0 += GBK) {
        // A tile: 128 rows x 32 cols, stored transposed
#pragma unroll
        for (int p = 0; p < 4; p++) {
            int f  = tid + 256 * p;            // 0..1023
            int m  = f >> 3;
            int kq = f & 7;
            float4 a4 = *reinterpret_cast<const float4*>(
                A + (size_t)(m0 + m) * CCH + k0 + kq * 4);
            float* d = sA + (kq * 4) * SAS + m;
            d[0 * SAS] = a4.x;
            d[1 * SAS] = a4.y;
            d[2 * SAS] = a4.z;
            d[3 * SAS] = a4.w;
        }
        // B tile: 32 rows x 64 cols
#pragma unroll
        for (int p = 0; p < 2; p++) {
            int f  = tid + 256 * p;            // 0..511
            int kr = f >> 4;
            int nq = f & 15;
            *reinterpret_cast<float4*>(sB + kr * GBN + nq * 4) =
                *reinterpret_cast<const float4*>(
                    B + (size_t)(k0 + kr) * N + n0 + nq * 4);
        }
        __syncthreads();

#pragma unroll
        for (int kk = 0; kk < GBK; kk++) {
            const float* ap = sA + kk * SAS + ty * 8;   // 8B-aligned (even offsets)
            unsigned long long a0 = *reinterpret_cast<const unsigned long long*>(ap + 0);
            unsigned long long a1 = *reinterpret_cast<const unsigned long long*>(ap + 2);
            unsigned long long a2 = *reinterpret_cast<const unsigned long long*>(ap + 4);
            unsigned long long a3 = *reinterpret_cast<const unsigned long long*>(ap + 6);
            float4 b4 = *reinterpret_cast<const float4*>(sB + kk * GBN + tx * 4);
            unsigned long long bd0 = dup2(b4.x);
            unsigned long long bd1 = dup2(b4.y);
            unsigned long long bd2 = dup2(b4.z);
            unsigned long long bd3 = dup2(b4.w);
            fma2(acc[0][0], a0, bd0); fma2(acc[0][1], a0, bd1);
            fma2(acc[0][2], a0, bd2); fma2(acc[0][3], a0, bd3);
            fma2(acc[1][0], a1, bd0); fma2(acc[1][1], a1, bd1);
            fma2(acc[1][2], a1, bd2); fma2(acc[1][3], a1, bd3);
            fma2(acc[2][0], a2, bd0); fma2(acc[2][1], a2, bd1);
            fma2(acc[2][2], a2, bd2); fma2(acc[2][3], a2, bd3);
            fma2(acc[3][0], a3, bd0); fma2(acc[3][1], a3, bd1);
            fma2(acc[3][2], a3, bd2); fma2(acc[3][3], a3, bd3);
        }
        __syncthreads();
    }

    float4 bv = make_float4(0.f, 0.f, 0.f, 0.f);
    if (bias) bv = *reinterpret_cast<const float4*>(bias + n0 + tx * 4);

#pragma unroll
    for (int i = 0; i < 4; i++) {
        float2 c0 = unpack2(acc[i][0]);
        float2 c1 = unpack2(acc[i][1]);
        float2 c2 = unpack2(acc[i][2]);
        float2 c3 = unpack2(acc[i][3]);
        int m = m0 + ty * 8 + 2 * i;
        float4 lo = make_float4(c0.x + bv.x, c1.x + bv.y, c2.x + bv.z, c3.x + bv.w);
        float4 hi = make_float4(c0.y + bv.x, c1.y + bv.y, c2.y + bv.z, c3.y + bv.w);
        *reinterpret_cast<float4*>(C + (size_t)m * N + n0 + tx * 4) = lo;
        *reinterpret_cast<float4*>(C + (size_t)(m + 1) * N + n0 + tx * 4) = hi;
    }
}

// input projections: z in {0,1,2} -> (Wsrc->g_asrc, Wdst->g_adst, Wval->g_val)
__global__ __launch_bounds__(256) void gemm_in_kernel(const float* __restrict__ x,
                                                      const float* __restrict__ Wsrc,
                                                      const float* __restrict__ Wdst,
                                                      const float* __restrict__ Wval) {
    const float* B;
    float* C;
    switch (blockIdx.z) {
        case 0:  B = Wsrc; C = g_asrc; break;
        case 1:  B = Wdst; C = g_adst; break;
        default: B = Wval; C = g_val;  break;
    }
    gemm_body<CCH>(x, B, nullptr, C, blockIdx.x * GBM, blockIdx.y * GBN);
}

// output projection: g_attn @ Wout + bout -> out
__global__ __launch_bounds__(256) void gemm_out_kernel(const float* __restrict__ Wout,
                                                       const float* __restrict__ bout,
                                                       float* __restrict__ out) {
    gemm_body<HOUT>(g_attn, Wout, bout, out, blockIdx.x * GBM, blockIdx.y * GBN);
}

// ---------------- attention: one row per 128-thread block, thread = channel ----------
__global__ __launch_bounds__(128) void attn_kernel(const float* __restrict__ pos,
                                                   const float* __restrict__ Wpos,
                                                   const float* __restrict__ bpos) {
    int row = blockIdx.x;          // b*NPTS + i
    int b   = row >> 12;
    int i   = row & (NPTS - 1);
    int c   = threadIdx.x;

    __shared__ float srel[KNNK][3];
    __shared__ int   sj[KNNK];

    if (c < KNNK) {
        int j = g_knn[(size_t)row * KNNK + c];
        sj[c] = j;
        const float* pb = pos + (size_t)b * NPTS * 3;
        srel[c][0] = pb[i * 3 + 0] - pb[j * 3 + 0];
        srel[c][1] = pb[i * 3 + 1] - pb[j * 3 + 1];
        srel[c][2] = pb[i * 3 + 2] - pb[j * 3 + 2];
    }
    __syncthreads();

    float w0 = Wpos[c];
    float w1 = Wpos[CCH + c];
    float w2 = Wpos[2 * CCH + c];
    float bp = bpos[c];
    float ad = g_adst[(size_t)row * CCH + c];

    float alpha[KNNK], vd[KNNK];
    float mx = -3.4e38f;
#pragma unroll
    for (int k = 0; k < KNNK; k++) {
        int j = sj[k];
        size_t base = ((size_t)b * NPTS + j) * CCH + c;
        float as = g_asrc[base];
        float vv = g_val[base];
        float dl = fmaf(srel[k][0], w0, fmaf(srel[k][1], w1, fmaf(srel[k][2], w2, bp)));
        alpha[k] = (ad - as) + dl;
        vd[k]    = vv + dl;
        mx = fmaxf(mx, alpha[k]);
    }
    float s = 0.f, accv = 0.f;
#pragma unroll
    for (int k = 0; k < KNNK; k++) {
        float e = __expf(alpha[k] - mx);
        s += e;
        accv = fmaf(e, vd[k], accv);
    }
    g_attn[(size_t)row * CCH + c] = accv / s;
}

// ---------------- launch (kernel launches ONLY — graph-capture safe) ----------------
extern "C" void kernel_launch(void* const* d_in, const int* in_sizes, int n_in,
                              void* d_out, int out_size) {
    const float* x    = (const float*)d_in[0];
    const float* pos  = (const float*)d_in[1];
    const float* Wsrc = (const float*)d_in[2];
    const float* Wdst = (const float*)d_in[3];
    const float* Wval = (const float*)d_in[4];
    const float* Wpos = (const float*)d_in[5];
    const float* bpos = (const float*)d_in[6];
    const float* Wout = (const float*)d_in[7];
    const float* bout = (const float*)d_in[8];
    float* out = (float*)d_out;

    knn_kernel<<<BATCH * (NPTS / 32), 256>>>(pos);

    dim3 g1(ROWS / GBM, CCH / GBN, 3);
    gemm_in_kernel<<<g1, 256>>>(x, Wsrc, Wdst, Wval);

    attn_kernel<<<ROWS, 128>>>(pos, Wpos, bpos);

    dim3 g2(ROWS / GBM, HOUT / GBN);
    gemm_out_kernel<<<g2, 256>>>(Wout, bout, out);
}

// round 13
// speedup vs baseline: 1.0149x; 1.0149x over previous
#include <cuda_runtime.h>
#include <cuda_bf16.h>
#include <cstdint>
#include <cstddef>

#define BATCH 8
#define NPTS  4096
#define CCH   128
#define HOUT  256
#define KNNK  16
#define ROWS  (BATCH * NPTS)

// ---------------- scratch (static __device__ — no runtime allocation) ----------------
__device__ float g_asrc[ROWS * CCH];
__device__ float g_adst[ROWS * CCH];
__device__ float g_val [ROWS * CCH];
__device__ float g_attn[ROWS * CCH];
__device__ int   g_knn [ROWS * KNNK];
// bf16 two-way splits
__device__ __nv_bfloat16 g_xh[ROWS * CCH], g_xl[ROWS * CCH];
__device__ __nv_bfloat16 g_ah[ROWS * CCH], g_al[ROWS * CCH];
__device__ __nv_bfloat16 g_wht[3 * CCH * CCH], g_wlt[3 * CCH * CCH];   // [n][k]
__device__ __nv_bfloat16 g_woht[HOUT * CCH], g_wolt[HOUT * CCH];       // [n][k]

// ---------------- KNN: warp per 4 rows (R10 measured-best form, unchanged) -----------
__global__ __launch_bounds__(256) void knn_kernel(const float* __restrict__ pos) {
    __shared__ float2 sxy[NPTS];   // 32 KB
    __shared__ float  szv[NPTS];   // 16 KB

    const int bpb = NPTS / 32;
    int b  = blockIdx.x / bpb;
    int rb = blockIdx.x % bpb;
    const float* pb = pos + (size_t)b * NPTS * 3;

    for (int t = threadIdx.x; t < NPTS; t += 256) {
        const float* p = pb + t * 3;
        sxy[t] = make_float2(p[0], p[1]);
        szv[t] = p[2];
    }
    __syncthreads();

    int warp = threadIdx.x >> 5;
    int lane = threadIdx.x & 31;
    const unsigned FULL = 0xffffffffu;
    int i0 = rb * 32 + warp * 4;

    float3 pi[4];
    unsigned long long cur[4], tk[4];
    float th[4];
#pragma unroll
    for (int r = 0; r < 4; r++) {
        float2 q = sxy[i0 + r];
        pi[r] = make_float3(q.x, q.y, szv[i0 + r]);
        cur[r] = ~0ull;
        tk[r]  = ~0ull;
        th[r]  = __int_as_float(0x7f800000);
    }

    for (int j0 = 0; j0 < NPTS; j0 += 32) {
        int j = j0 + lane;
        float2 pj = sxy[j];
        float  zj = szv[j];
#pragma unroll
        for (int r = 0; r < 4; r++) {
            float dx = pi[r].x - pj.x;
            float dy = pi[r].y - pj.y;
            float dz = pi[r].z - zj;
            float d2 = fmaf(dx, dx, fmaf(dy, dy, dz * dz));

            unsigned mask = __ballot_sync(FULL, d2 <= th[r]);
            if (mask) {
                unsigned long long key =
                    ((unsigned long long)__float_as_uint(d2) << 32) | (unsigned)j;
                bool changed = false;
                while (mask) {
                    int src = __ffs(mask) - 1;
                    mask &= mask - 1;
                    unsigned long long cand = __shfl_sync(FULL, key, src);
                    if (cand < tk[r]) {
                        unsigned long long prev = __shfl_up_sync(FULL, cur[r], 1);
                        bool bigger = cur[r] > cand;
                        unsigned long long ins =
                            (lane > 0 && prev > cand) ? prev : cand;
                        cur[r] = bigger ? ins : cur[r];
                        changed = true;
                    }
                }
                if (changed) {
                    tk[r] = __shfl_sync(FULL, cur[r], 15);
                    th[r] = __uint_as_float((unsigned)(tk[r] >> 32));
                }
            }
        }
    }

    if (lane < KNNK) {
#pragma unroll
        for (int r = 0; r < 4; r++)
            g_knn[((size_t)b * NPTS + i0 + r) * KNNK + lane] =
                (int)(unsigned)(cur[r] & 0xffffffffu);
    }
}

// ---------------- bf16 two-way split kernels ----------------
__device__ __forceinline__ void split_one(float v, __nv_bfloat16* h, __nv_bfloat16* l) {
    __nv_bfloat16 hi = __float2bfloat16(v);
    *h = hi;
    *l = __float2bfloat16(v - __bfloat162float(hi));
}

__global__ __launch_bounds__(256) void split_x_kernel(const float* __restrict__ x) {
    int i = blockIdx.x * 256 + threadIdx.x;
    split_one(x[i], &g_xh[i], &g_xl[i]);
}
__global__ __launch_bounds__(256) void split_attn_kernel() {
    int i = blockIdx.x * 256 + threadIdx.x;
    split_one(g_attn[i], &g_ah[i], &g_al[i]);
}
// transpose-split W: src [128 k][N n] fp32 -> dst [N][128] bf16 (h, l)
__global__ __launch_bounds__(256) void split_w_kernel(const float* __restrict__ s0,
                                                      const float* __restrict__ s1,
                                                      const float* __restrict__ s2,
                                                      const float* __restrict__ s3) {
    int w = blockIdx.y;
    const float* src = (w == 0) ? s0 : (w == 1) ? s1 : (w == 2) ? s2 : s3;
    int N = (w < 3) ? CCH : HOUT;
    __nv_bfloat16* h = (w < 3) ? g_wht + w * CCH * CCH : g_woht;
    __nv_bfloat16* l = (w < 3) ? g_wlt + w * CCH * CCH : g_wolt;
    int i = blockIdx.x * 256 + threadIdx.x;
    if (i < CCH * N) {
        int k = i / N, n = i % N;
        split_one(src[i], &h[n * CCH + k], &l[n * CCH + k]);
    }
}

// ---------------- HMMA GEMM: C[M x NTOT] = A @ W^T(+bias), bf16 split x3 --------------
// mma.sync.aligned.m16n8k16.row.col.f32.bf16.bf16.f32 (baseline sm_80+ feature).
// Block 256 thr, tile 128M x 64N; warp = 32M x 32N (2 m-tiles x 4 n-tiles).
// K=128 in 4 chunks of 32. smem tiles padded to stride 40 bf16 (conflict-free frags).
#define AST 40   // padded bf16 stride for 32-wide k-chunk rows

__device__ __forceinline__ void hmma(float* c, const uint32_t* a, const uint32_t* b) {
    asm volatile(
        "mma.sync.aligned.m16n8k16.row.col.f32.bf16.bf16.f32 "
        "{%0,%1,%2,%3}, {%4,%5,%6,%7}, {%8,%9}, {%0,%1,%2,%3};"
        : "+f"(c[0]), "+f"(c[1]), "+f"(c[2]), "+f"(c[3])
        : "r"(a[0]), "r"(a[1]), "r"(a[2]), "r"(a[3]), "r"(b[0]), "r"(b[1]));
}

__device__ __forceinline__ void stage_tile(const __nv_bfloat16* __restrict__ g,
                                           int row0, int k0, int rows,
                                           __nv_bfloat16* dst) {
    for (int u = threadIdx.x; u < rows * 4; u += 256) {
        int row = u >> 2, seg = u & 3;   // seg*8 bf16 = 16B
        uint4 v = *reinterpret_cast<const uint4*>(
            g + (size_t)(row0 + row) * CCH + k0 + seg * 8);
        *reinterpret_cast<uint4*>(dst + row * AST + seg * 8) = v;
    }
}

__device__ __forceinline__ uint32_t lds32(const __nv_bfloat16* p) {
    return *reinterpret_cast<const uint32_t*>(p);
}

__device__ __forceinline__ void gemm_mma_body(const __nv_bfloat16* __restrict__ Ah,
                                              const __nv_bfloat16* __restrict__ Al,
                                              const __nv_bfloat16* __restrict__ Wh,
                                              const __nv_bfloat16* __restrict__ Wl,
                                              const float* __restrict__ bias,
                                              float* __restrict__ C, int NTOT) {
    __shared__ __nv_bfloat16 sAh[128 * AST];   // 10240 B
    __shared__ __nv_bfloat16 sAl[128 * AST];   // 10240 B
    __shared__ __nv_bfloat16 sWh[64 * AST];    //  5120 B
    __shared__ __nv_bfloat16 sWl[64 * AST];    //  5120 B

    int tid = threadIdx.x, wid = tid >> 5, lane = tid & 31;
    int m0 = blockIdx.x * 128, n0 = blockIdx.y * 64;
    int wm = (wid & 3) * 32;     // warp row offset in tile
    int wn = (wid >> 2) * 32;    // warp col offset in tile
    int r  = lane >> 2;          // 0..7
    int cq = (lane & 3) * 2;     // 0,2,4,6

    float acc[2][4][4];
#pragma unroll
    for (int i = 0; i < 2; i++)
#pragma unroll
        for (int j = 0; j < 4; j++)
#pragma unroll
            for (int q = 0; q < 4; q++) acc[i][j][q] = 0.f;

    for (int kc = 0; kc < 4; kc++) {
        int k0 = kc * 32;
        stage_tile(Ah, m0, k0, 128, sAh);
        stage_tile(Al, m0, k0, 128, sAl);
        stage_tile(Wh, n0, k0, 64,  sWh);
        stage_tile(Wl, n0, k0, 64,  sWl);
        __syncthreads();

#pragma unroll
        for (int ks = 0; ks < 2; ks++) {
            int kk = ks * 16;
            uint32_t fah[2][4], fal[2][4];
#pragma unroll
            for (int tm = 0; tm < 2; tm++) {
                const __nv_bfloat16* base = sAh + (wm + tm * 16 + r) * AST + kk + cq;
                const __nv_bfloat16* basl = sAl + (wm + tm * 16 + r) * AST + kk + cq;
                fah[tm][0] = lds32(base);
                fah[tm][1] = lds32(base + 8 * AST);
                fah[tm][2] = lds32(base + 8);
                fah[tm][3] = lds32(base + 8 * AST + 8);
                fal[tm][0] = lds32(basl);
                fal[tm][1] = lds32(basl + 8 * AST);
                fal[tm][2] = lds32(basl + 8);
                fal[tm][3] = lds32(basl + 8 * AST + 8);
            }
            uint32_t fbh[4][2], fbl[4][2];
#pragma unroll
            for (int tn = 0; tn < 4; tn++) {
                const __nv_bfloat16* base = sWh + (wn + tn * 8 + r) * AST + kk + cq;
                const __nv_bfloat16* basl = sWl + (wn + tn * 8 + r) * AST + kk + cq;
                fbh[tn][0] = lds32(base);
                fbh[tn][1] = lds32(base + 8);
                fbl[tn][0] = lds32(basl);
                fbl[tn][1] = lds32(basl + 8);
            }
#pragma unroll
            for (int tm = 0; tm < 2; tm++)
#pragma unroll
                for (int tn = 0; tn < 4; tn++) {
                    hmma(acc[tm][tn], fah[tm], fbh[tn]);
                    hmma(acc[tm][tn], fah[tm], fbl[tn]);
                    hmma(acc[tm][tn], fal[tm], fbh[tn]);
                }
        }
        __syncthreads();
    }

#pragma unroll
    for (int tm = 0; tm < 2; tm++)
#pragma unroll
        for (int tn = 0; tn < 4; tn++) {
            int m = m0 + wm + tm * 16 + r;
            int n = n0 + wn + tn * 8 + cq;
            float bv0 = 0.f, bv1 = 0.f;
            if (bias) { bv0 = bias[n]; bv1 = bias[n + 1]; }
            float2 lo = make_float2(acc[tm][tn][0] + bv0, acc[tm][tn][1] + bv1);
            float2 hi = make_float2(acc[tm][tn][2] + bv0, acc[tm][tn][3] + bv1);
            *reinterpret_cast<float2*>(C + (size_t)m * NTOT + n) = lo;
            *reinterpret_cast<float2*>(C + (size_t)(m + 8) * NTOT + n) = hi;
        }
}

__global__ __launch_bounds__(256) void gemm_mma_in_kernel() {
    int z = blockIdx.z;
    const __nv_bfloat16* wh = g_wht + z * CCH * CCH;
    const __nv_bfloat16* wl = g_wlt + z * CCH * CCH;
    float* C = (z == 0) ? g_asrc : (z == 1) ? g_adst : g_val;
    gemm_mma_body(g_xh, g_xl, wh, wl, nullptr, C, CCH);
}
__global__ __launch_bounds__(256) void gemm_mma_out_kernel(const float* __restrict__ bout,
                                                           float* __restrict__ out) {
    gemm_mma_body(g_ah, g_al, g_woht, g_wolt, bout, out, HOUT);
}

// ---------------- attention: one row per 128-thread block (unchanged) ----------------
__global__ __launch_bounds__(128) void attn_kernel(const float* __restrict__ pos,
                                                   const float* __restrict__ Wpos,
                                                   const float* __restrict__ bpos) {
    int row = blockIdx.x;
    int b   = row >> 12;
    int i   = row & (NPTS - 1);
    int c   = threadIdx.x;

    __shared__ float srel[KNNK][3];
    __shared__ int   sj[KNNK];

    if (c < KNNK) {
        int j = g_knn[(size_t)row * KNNK + c];
        sj[c] = j;
        const float* pb = pos + (size_t)b * NPTS * 3;
        srel[c][0] = pb[i * 3 + 0] - pb[j * 3 + 0];
        srel[c][1] = pb[i * 3 + 1] - pb[j * 3 + 1];
        srel[c][2] = pb[i * 3 + 2] - pb[j * 3 + 2];
    }
    __syncthreads();

    float w0 = Wpos[c];
    float w1 = Wpos[CCH + c];
    float w2 = Wpos[2 * CCH + c];
    float bp = bpos[c];
    float ad = g_adst[(size_t)row * CCH + c];

    float alpha[KNNK], vd[KNNK];
    float mx = -3.4e38f;
#pragma unroll
    for (int k = 0; k < KNNK; k++) {
        int j = sj[k];
        size_t base = ((size_t)b * NPTS + j) * CCH + c;
        float as = g_asrc[base];
        float vv = g_val[base];
        float dl = fmaf(srel[k][0], w0, fmaf(srel[k][1], w1, fmaf(srel[k][2], w2, bp)));
        alpha[k] = (ad - as) + dl;
        vd[k]    = vv + dl;
        mx = fmaxf(mx, alpha[k]);
    }
    float s = 0.f, accv = 0.f;
#pragma unroll
    for (int k = 0; k < KNNK; k++) {
        float e = __expf(alpha[k] - mx);
        s += e;
        accv = fmaf(e, vd[k], accv);
    }
    g_attn[(size_t)row * CCH + c] = accv / s;
}

// ---------------- launch (kernel launches ONLY — graph-capture safe) ----------------
extern "C" void kernel_launch(void* const* d_in, const int* in_sizes, int n_in,
                              void* d_out, int out_size) {
    const float* x    = (const float*)d_in[0];
    const float* pos  = (const float*)d_in[1];
    const float* Wsrc = (const float*)d_in[2];
    const float* Wdst = (const float*)d_in[3];
    const float* Wval = (const float*)d_in[4];
    const float* Wpos = (const float*)d_in[5];
    const float* bpos = (const float*)d_in[6];
    const float* Wout = (const float*)d_in[7];
    const float* bout = (const float*)d_in[8];
    float* out = (float*)d_out;

    knn_kernel<<<BATCH * (NPTS / 32), 256>>>(pos);

    split_x_kernel<<<ROWS * CCH / 256, 256>>>(x);
    split_w_kernel<<<dim3(CCH * HOUT / 256, 4), 256>>>(Wsrc, Wdst, Wval, Wout);

    gemm_mma_in_kernel<<<dim3(ROWS / 128, CCH / 64, 3), 256>>>();

    attn_kernel<<<ROWS, 128>>>(pos, Wpos, bpos);

    split_attn_kernel<<<ROWS * CCH / 256, 256>>>();

    gemm_mma_out_kernel<<<dim3(ROWS / 128, HOUT / 64), 256>>>(bout, out);
}

// round 14
// speedup vs baseline: 1.0416x; 1.0263x over previous
#include <cuda_runtime.h>
#include <cuda_bf16.h>
#include <cstdint>
#include <cstddef>

#define BATCH 8
#define NPTS  4096
#define CCH   128
#define HOUT  256
#define KNNK  16
#define ROWS  (BATCH * NPTS)

// ---------------- scratch (static __device__ — no runtime allocation) ----------------
__device__ float g_asrc[ROWS * CCH];
__device__ float g_adst[ROWS * CCH];
__device__ float g_val [ROWS * CCH];
__device__ int   g_knn [ROWS * KNNK];
// bf16 two-way splits
__device__ __nv_bfloat16 g_xh[ROWS * CCH], g_xl[ROWS * CCH];
__device__ __nv_bfloat16 g_ah[ROWS * CCH], g_al[ROWS * CCH];   // written by attn (fused split)
__device__ __nv_bfloat16 g_wht[3 * CCH * CCH], g_wlt[3 * CCH * CCH];   // [n][k]
__device__ __nv_bfloat16 g_woht[HOUT * CCH], g_wolt[HOUT * CCH];       // [n][k]

// ---------------- KNN: warp per 4 rows (R10 measured-best form, unchanged) -----------
__global__ __launch_bounds__(256) void knn_kernel(const float* __restrict__ pos) {
    __shared__ float2 sxy[NPTS];   // 32 KB
    __shared__ float  szv[NPTS];   // 16 KB

    const int bpb = NPTS / 32;
    int b  = blockIdx.x / bpb;
    int rb = blockIdx.x % bpb;
    const float* pb = pos + (size_t)b * NPTS * 3;

    for (int t = threadIdx.x; t < NPTS; t += 256) {
        const float* p = pb + t * 3;
        sxy[t] = make_float2(p[0], p[1]);
        szv[t] = p[2];
    }
    __syncthreads();

    int warp = threadIdx.x >> 5;
    int lane = threadIdx.x & 31;
    const unsigned FULL = 0xffffffffu;
    int i0 = rb * 32 + warp * 4;

    float3 pi[4];
    unsigned long long cur[4], tk[4];
    float th[4];
#pragma unroll
    for (int r = 0; r < 4; r++) {
        float2 q = sxy[i0 + r];
        pi[r] = make_float3(q.x, q.y, szv[i0 + r]);
        cur[r] = ~0ull;
        tk[r]  = ~0ull;
        th[r]  = __int_as_float(0x7f800000);
    }

    for (int j0 = 0; j0 < NPTS; j0 += 32) {
        int j = j0 + lane;
        float2 pj = sxy[j];
        float  zj = szv[j];
#pragma unroll
        for (int r = 0; r < 4; r++) {
            float dx = pi[r].x - pj.x;
            float dy = pi[r].y - pj.y;
            float dz = pi[r].z - zj;
            float d2 = fmaf(dx, dx, fmaf(dy, dy, dz * dz));

            unsigned mask = __ballot_sync(FULL, d2 <= th[r]);
            if (mask) {
                unsigned long long key =
                    ((unsigned long long)__float_as_uint(d2) << 32) | (unsigned)j;
                bool changed = false;
                while (mask) {
                    int src = __ffs(mask) - 1;
                    mask &= mask - 1;
                    unsigned long long cand = __shfl_sync(FULL, key, src);
                    if (cand < tk[r]) {
                        unsigned long long prev = __shfl_up_sync(FULL, cur[r], 1);
                        bool bigger = cur[r] > cand;
                        unsigned long long ins =
                            (lane > 0 && prev > cand) ? prev : cand;
                        cur[r] = bigger ? ins : cur[r];
                        changed = true;
                    }
                }
                if (changed) {
                    tk[r] = __shfl_sync(FULL, cur[r], 15);
                    th[r] = __uint_as_float((unsigned)(tk[r] >> 32));
                }
            }
        }
    }

    if (lane < KNNK) {
#pragma unroll
        for (int r = 0; r < 4; r++)
            g_knn[((size_t)b * NPTS + i0 + r) * KNNK + lane] =
                (int)(unsigned)(cur[r] & 0xffffffffu);
    }
}

// ---------------- bf16 two-way split kernels ----------------
__device__ __forceinline__ void split_one(float v, __nv_bfloat16* h, __nv_bfloat16* l) {
    __nv_bfloat16 hi = __float2bfloat16(v);
    *h = hi;
    *l = __float2bfloat16(v - __bfloat162float(hi));
}

__global__ __launch_bounds__(256) void split_x_kernel(const float* __restrict__ x) {
    int i = blockIdx.x * 256 + threadIdx.x;
    split_one(x[i], &g_xh[i], &g_xl[i]);
}
// transpose-split W: src [128 k][N n] fp32 -> dst [N][128] bf16 (h, l)
__global__ __launch_bounds__(256) void split_w_kernel(const float* __restrict__ s0,
                                                      const float* __restrict__ s1,
                                                      const float* __restrict__ s2,
                                                      const float* __restrict__ s3) {
    int w = blockIdx.y;
    const float* src = (w == 0) ? s0 : (w == 1) ? s1 : (w == 2) ? s2 : s3;
    int N = (w < 3) ? CCH : HOUT;
    __nv_bfloat16* h = (w < 3) ? g_wht + w * CCH * CCH : g_woht;
    __nv_bfloat16* l = (w < 3) ? g_wlt + w * CCH * CCH : g_wolt;
    int i = blockIdx.x * 256 + threadIdx.x;
    if (i < CCH * N) {
        int k = i / N, n = i % N;
        split_one(src[i], &h[n * CCH + k], &l[n * CCH + k]);
    }
}

// ---------------- HMMA GEMM (R13-exact): C = A @ W^T (+bias), bf16 split x3 ----------
#define AST 40   // padded bf16 stride for 32-wide k-chunk rows

__device__ __forceinline__ void hmma(float* c, const uint32_t* a, const uint32_t* b) {
    asm volatile(
        "mma.sync.aligned.m16n8k16.row.col.f32.bf16.bf16.f32 "
        "{%0,%1,%2,%3}, {%4,%5,%6,%7}, {%8,%9}, {%0,%1,%2,%3};"
        : "+f"(c[0]), "+f"(c[1]), "+f"(c[2]), "+f"(c[3])
        : "r"(a[0]), "r"(a[1]), "r"(a[2]), "r"(a[3]), "r"(b[0]), "r"(b[1]));
}

__device__ __forceinline__ void stage_tile(const __nv_bfloat16* __restrict__ g,
                                           int row0, int k0, int rows,
                                           __nv_bfloat16* dst) {
    for (int u = threadIdx.x; u < rows * 4; u += 256) {
        int row = u >> 2, seg = u & 3;
        uint4 v = *reinterpret_cast<const uint4*>(
            g + (size_t)(row0 + row) * CCH + k0 + seg * 8);
        *reinterpret_cast<uint4*>(dst + row * AST + seg * 8) = v;
    }
}

__device__ __forceinline__ uint32_t lds32(const __nv_bfloat16* p) {
    return *reinterpret_cast<const uint32_t*>(p);
}

__device__ __forceinline__ void gemm_mma_body(const __nv_bfloat16* __restrict__ Ah,
                                              const __nv_bfloat16* __restrict__ Al,
                                              const __nv_bfloat16* __restrict__ Wh,
                                              const __nv_bfloat16* __restrict__ Wl,
                                              const float* __restrict__ bias,
                                              float* __restrict__ C, int NTOT) {
    __shared__ __nv_bfloat16 sAh[128 * AST];
    __shared__ __nv_bfloat16 sAl[128 * AST];
    __shared__ __nv_bfloat16 sWh[64 * AST];
    __shared__ __nv_bfloat16 sWl[64 * AST];

    int tid = threadIdx.x, wid = tid >> 5, lane = tid & 31;
    int m0 = blockIdx.x * 128, n0 = blockIdx.y * 64;
    int wm = (wid & 3) * 32;
    int wn = (wid >> 2) * 32;
    int r  = lane >> 2;
    int cq = (lane & 3) * 2;

    float acc[2][4][4];
#pragma unroll
    for (int i = 0; i < 2; i++)
#pragma unroll
        for (int j = 0; j < 4; j++)
#pragma unroll
            for (int q = 0; q < 4; q++) acc[i][j][q] = 0.f;

    for (int kc = 0; kc < 4; kc++) {
        int k0 = kc * 32;
        stage_tile(Ah, m0, k0, 128, sAh);
        stage_tile(Al, m0, k0, 128, sAl);
        stage_tile(Wh, n0, k0, 64,  sWh);
        stage_tile(Wl, n0, k0, 64,  sWl);
        __syncthreads();

#pragma unroll
        for (int ks = 0; ks < 2; ks++) {
            int kk = ks * 16;
            uint32_t fah[2][4], fal[2][4];
#pragma unroll
            for (int tm = 0; tm < 2; tm++) {
                const __nv_bfloat16* base = sAh + (wm + tm * 16 + r) * AST + kk + cq;
                const __nv_bfloat16* basl = sAl + (wm + tm * 16 + r) * AST + kk + cq;
                fah[tm][0] = lds32(base);
                fah[tm][1] = lds32(base + 8 * AST);
                fah[tm][2] = lds32(base + 8);
                fah[tm][3] = lds32(base + 8 * AST + 8);
                fal[tm][0] = lds32(basl);
                fal[tm][1] = lds32(basl + 8 * AST);
                fal[tm][2] = lds32(basl + 8);
                fal[tm][3] = lds32(basl + 8 * AST + 8);
            }
            uint32_t fbh[4][2], fbl[4][2];
#pragma unroll
            for (int tn = 0; tn < 4; tn++) {
                const __nv_bfloat16* base = sWh + (wn + tn * 8 + r) * AST + kk + cq;
                const __nv_bfloat16* basl = sWl + (wn + tn * 8 + r) * AST + kk + cq;
                fbh[tn][0] = lds32(base);
                fbh[tn][1] = lds32(base + 8);
                fbl[tn][0] = lds32(basl);
                fbl[tn][1] = lds32(basl + 8);
            }
#pragma unroll
            for (int tm = 0; tm < 2; tm++)
#pragma unroll
                for (int tn = 0; tn < 4; tn++) {
                    hmma(acc[tm][tn], fah[tm], fbh[tn]);
                    hmma(acc[tm][tn], fah[tm], fbl[tn]);
                    hmma(acc[tm][tn], fal[tm], fbh[tn]);
                }
        }
        __syncthreads();
    }

#pragma unroll
    for (int tm = 0; tm < 2; tm++)
#pragma unroll
        for (int tn = 0; tn < 4; tn++) {
            int m = m0 + wm + tm * 16 + r;
            int n = n0 + wn + tn * 8 + cq;
            float bv0 = 0.f, bv1 = 0.f;
            if (bias) { bv0 = bias[n]; bv1 = bias[n + 1]; }
            float2 lo = make_float2(acc[tm][tn][0] + bv0, acc[tm][tn][1] + bv1);
            float2 hi = make_float2(acc[tm][tn][2] + bv0, acc[tm][tn][3] + bv1);
            *reinterpret_cast<float2*>(C + (size_t)m * NTOT + n) = lo;
            *reinterpret_cast<float2*>(C + (size_t)(m + 8) * NTOT + n) = hi;
        }
}

__global__ __launch_bounds__(256) void gemm_mma_in_kernel() {
    int z = blockIdx.z;
    const __nv_bfloat16* wh = g_wht + z * CCH * CCH;
    const __nv_bfloat16* wl = g_wlt + z * CCH * CCH;
    float* C = (z == 0) ? g_asrc : (z == 1) ? g_adst : g_val;
    gemm_mma_body(g_xh, g_xl, wh, wl, nullptr, C, CCH);
}
__global__ __launch_bounds__(256) void gemm_mma_out_kernel(const float* __restrict__ bout,
                                                           float* __restrict__ out) {
    gemm_mma_body(g_ah, g_al, g_woht, g_wolt, bout, out, HOUT);
}

// ---------------- attention + fused bf16 split of the result ----------------
__global__ __launch_bounds__(128) void attn_kernel(const float* __restrict__ pos,
                                                   const float* __restrict__ Wpos,
                                                   const float* __restrict__ bpos) {
    int row = blockIdx.x;
    int b   = row >> 12;
    int i   = row & (NPTS - 1);
    int c   = threadIdx.x;

    __shared__ float srel[KNNK][3];
    __shared__ int   sj[KNNK];

    if (c < KNNK) {
        int j = g_knn[(size_t)row * KNNK + c];
        sj[c] = j;
        const float* pb = pos + (size_t)b * NPTS * 3;
        srel[c][0] = pb[i * 3 + 0] - pb[j * 3 + 0];
        srel[c][1] = pb[i * 3 + 1] - pb[j * 3 + 1];
        srel[c][2] = pb[i * 3 + 2] - pb[j * 3 + 2];
    }
    __syncthreads();

    float w0 = Wpos[c];
    float w1 = Wpos[CCH + c];
    float w2 = Wpos[2 * CCH + c];
    float bp = bpos[c];
    float ad = g_adst[(size_t)row * CCH + c];

    float alpha[KNNK], vd[KNNK];
    float mx = -3.4e38f;
#pragma unroll
    for (int k = 0; k < KNNK; k++) {
        int j = sj[k];
        size_t base = ((size_t)b * NPTS + j) * CCH + c;
        float as = g_asrc[base];
        float vv = g_val[base];
        float dl = fmaf(srel[k][0], w0, fmaf(srel[k][1], w1, fmaf(srel[k][2], w2, bp)));
        alpha[k] = (ad - as) + dl;
        vd[k]    = vv + dl;
        mx = fmaxf(mx, alpha[k]);
    }
    float s = 0.f, accv = 0.f;
#pragma unroll
    for (int k = 0; k < KNNK; k++) {
        float e = __expf(alpha[k] - mx);
        s += e;
        accv = fmaf(e, vd[k], accv);
    }
    float v = accv / s;
    size_t o = (size_t)row * CCH + c;
    split_one(v, &g_ah[o], &g_al[o]);     // fused split (removes split_attn kernel)
}

// ---------------- launch (kernel launches ONLY — graph-capture safe) ----------------
// Order chosen so knn_kernel is the 4th launch -> gets captured by the profiler.
extern "C" void kernel_launch(void* const* d_in, const int* in_sizes, int n_in,
                              void* d_out, int out_size) {
    const float* x    = (const float*)d_in[0];
    const float* pos  = (const float*)d_in[1];
    const float* Wsrc = (const float*)d_in[2];
    const float* Wdst = (const float*)d_in[3];
    const float* Wval = (const float*)d_in[4];
    const float* Wpos = (const float*)d_in[5];
    const float* bpos = (const float*)d_in[6];
    const float* Wout = (const float*)d_in[7];
    const float* bout = (const float*)d_in[8];
    float* out = (float*)d_out;

    split_x_kernel<<<ROWS * CCH / 256, 256>>>(x);                       // 1
    split_w_kernel<<<dim3(CCH * HOUT / 256, 4), 256>>>(Wsrc, Wdst, Wval, Wout); // 2
    gemm_mma_in_kernel<<<dim3(ROWS / 128, CCH / 64, 3), 256>>>();       // 3
    knn_kernel<<<BATCH * (NPTS / 32), 256>>>(pos);                      // 4  <- profiled
    attn_kernel<<<ROWS, 128>>>(pos, Wpos, bpos);                        // 5
    gemm_mma_out_kernel<<<dim3(ROWS / 128, HOUT / 64), 256>>>(bout, out); // 6
}